// round 1
// baseline (speedup 1.0000x reference)
#include <cuda_runtime.h>

#define PI_D 3.14159265358979323846
#define NN   512
#define N2   262144
#define NIMG 144
#define LSTRIDE 584
#define SK(i) ((i) + ((i)>>3))

// ---------------- device scratch (no allocations allowed) ----------------
static __device__ float2 d_field[(size_t)NIMG*N2];   // ~302 MB, in-place field
static __device__ float  d_intens[(size_t)NIMG*N2];  // ~151 MB, per-mode intensity
static __device__ float2 d_Tl[3*N2];                 // layer transmissions
static __device__ float2 d_Hb[N2];                   // H / N^2
static __device__ float2 d_Hb2[N2];                  // H^2 / N^2
static __device__ float2 d_tw[NN];                   // e^{-2pi i k/512}
static __device__ unsigned char d_cls[N2];           // pixel -> class (255 = none)
static __device__ float d_part[NIMG*64*10];          // partial sums

__device__ __forceinline__ float2 cmul(float2 a, float2 b){
    return make_float2(a.x*b.x - a.y*b.y, a.x*b.y + a.y*b.x);
}

// ---------------- radix-8 butterfly (DIF, output bit-reversed) ----------------
template<bool INV>
__device__ __forceinline__ void fft8(float2 v[8]){
    const float C0 = 0.70710678118654752440f;
    float2 t;
#define BTF(a,b) { t = a; a.x = t.x + b.x; a.y = t.y + b.y; b.x = t.x - b.x; b.y = t.y - b.y; }
    BTF(v[0],v[4]); BTF(v[1],v[5]); BTF(v[2],v[6]); BTF(v[3],v[7]);
    if (INV){
        v[5] = cmul(v[5], make_float2(C0,  C0));
        v[6] = make_float2(-v[6].y,  v[6].x);
        v[7] = cmul(v[7], make_float2(-C0, C0));
    } else {
        v[5] = cmul(v[5], make_float2(C0, -C0));
        v[6] = make_float2( v[6].y, -v[6].x);
        v[7] = cmul(v[7], make_float2(-C0,-C0));
    }
    BTF(v[0],v[2]); BTF(v[1],v[3]); BTF(v[4],v[6]); BTF(v[5],v[7]);
    if (INV){ v[3] = make_float2(-v[3].y, v[3].x); v[7] = make_float2(-v[7].y, v[7].x); }
    else    { v[3] = make_float2( v[3].y,-v[3].x); v[7] = make_float2( v[7].y,-v[7].x); }
    BTF(v[0],v[1]); BTF(v[2],v[3]); BTF(v[4],v[5]); BTF(v[6],v[7]);
#undef BTF
}

// ---------------- 512-pt Stockham FFT, 64 threads per line ----------------
template<bool INV>
__device__ __forceinline__ void fft512(float2* s, int j, const float2* tw){
    const int brev[8] = {0,4,2,6,1,5,3,7};
#pragma unroll
    for (int stage=0; stage<3; stage++){
        const int Ns = (stage==0)?1:((stage==1)?8:64);
        float2 v[8];
#pragma unroll
        for (int r=0;r<8;r++) v[r] = s[SK(j + (r<<6))];
        int jm = j & (Ns-1);
        int tb = jm * (NN/(Ns*8));
#pragma unroll
        for (int r=1;r<8;r++){
            float2 w = tw[r*tb];
            if (INV) w.y = -w.y;
            v[r] = cmul(v[r], w);
        }
        fft8<INV>(v);
        __syncthreads();
        int idxD = ((j - jm) << 3) + jm;
#pragma unroll
        for (int r=0;r<8;r++) s[SK(idxD + r*Ns)] = v[brev[r]];
        __syncthreads();
    }
}

// ---------------- init kernels ----------------
__global__ void k_tw(){
    int t = threadIdx.x;
    double ang = -2.0*PI_D*(double)t/512.0;
    d_tw[t] = make_float2((float)cos(ang), (float)sin(ang));
}

__global__ void k_H(){
    int i = blockIdx.x, j = threadIdx.x;
    float inv = 1.0f/(512.0f*8e-6f);
    float fx = (float)(i<256 ? i : i-512) * inv;
    float fy = (float)(j<256 ? j : j-512) * inv;
    const float lam = 5.32e-7f;
    float lx = lam*fx, ly = lam*fy;
    float arg = 1.0f - lx*lx - ly*ly;
    float sa = sqrtf(fmaxf(arg, 0.0f));
    const float KZ = (float)(2.0*PI_D/5.32e-7*0.05);  // matches jax f32 path
    float phi = KZ * sa;                               // f32 rounding, like reference
    double s, c;
    sincos((double)phi, &s, &c);                       // accurate for huge args
    float hr = (float)c, hi = (float)s;
    const float sc = 1.0f/262144.0f;
    d_Hb [i*NN+j] = make_float2(hr*sc, hi*sc);
    d_Hb2[i*NN+j] = make_float2((hr*hr - hi*hi)*sc, 2.0f*hr*hi*sc);
}

__global__ void k_T(const float* __restrict__ amp, const float* __restrict__ phs){
    int idx = blockIdx.x*512 + threadIdx.x;            // 3*N2 total
    float a = amp[idx], p = phs[idx];
    float s, c; sincosf(p, &s, &c);
    d_Tl[idx] = make_float2(a*c, a*s);
}

__global__ void k_cls(const float* __restrict__ mask){
    int p = blockIdx.x*512 + threadIdx.x;
    unsigned char c = 255;
#pragma unroll
    for (int j=0;j<10;j++) if (mask[j*N2 + p] > 0.5f) c = (unsigned char)j;
    d_cls[p] = c;
}

// ---------------- pass kernels ----------------
// P1: build E0*T0, row forward FFT
__global__ void __launch_bounds__(256) p1_row(const float* __restrict__ xamp,
                                              const float* __restrict__ pn){
    __shared__ float2 S[4*LSTRIDE];
    __shared__ float2 TW[NN];
    int t = threadIdx.x;
    TW[t] = d_tw[t]; TW[t+256] = d_tw[t+256];
    int img  = blockIdx.x >> 7;
    int row0 = (blockIdx.x & 127) << 2;
    int b = img & 15, m = img >> 4;
    float fm = 0.5f * (float)(m+1);
    size_t ibase = (size_t)img*N2 + (size_t)row0*NN;
    size_t bbase = (size_t)b  *N2 + (size_t)row0*NN;
#pragma unroll
    for (int k=0;k<8;k++){
        int e = t + (k<<8);
        float p  = pn  [ibase + e];
        float xa = xamp[bbase + e];
        float sn, cs; __sincosf(p*fm, &sn, &cs);
        float2 ein = make_float2(xa*cs, xa*sn);
        float2 T0  = d_Tl[row0*NN + e];
        S[(e>>9)*LSTRIDE + SK(e & 511)] = cmul(ein, T0);
    }
    __syncthreads();
    fft512<false>(S + (t>>6)*LSTRIDE, t & 63, TW);
#pragma unroll
    for (int k=0;k<8;k++){
        int e = t + (k<<8);
        d_field[ibase + e] = S[(e>>9)*LSTRIDE + SK(e & 511)];
    }
}

// P2/P4/P6: col forward FFT, * H (or H^2) (incl. 1/N^2), col inverse FFT
__global__ void __launch_bounds__(256) col_pass(int h2){
    __shared__ float2 S[4*LSTRIDE];
    __shared__ float2 TW[NN];
    int t = threadIdx.x;
    TW[t] = d_tw[t]; TW[t+256] = d_tw[t+256];
    int img = blockIdx.x >> 7;
    int x0  = (blockIdx.x & 127) << 2;
    size_t ibase = (size_t)img*N2;
#pragma unroll
    for (int k=0;k<8;k++){
        int y = (t>>2) + (k<<6);
        int c = t & 3;
        S[c*LSTRIDE + SK(y)] = d_field[ibase + (size_t)y*NN + x0 + c];
    }
    __syncthreads();
    fft512<false>(S + (t>>6)*LSTRIDE, t & 63, TW);
    const float2* __restrict__ Hm = h2 ? d_Hb2 : d_Hb;
#pragma unroll
    for (int k=0;k<8;k++){
        int y = (t>>2) + (k<<6);
        int c = t & 3;
        int si = c*LSTRIDE + SK(y);
        S[si] = cmul(S[si], Hm[y*NN + x0 + c]);
    }
    __syncthreads();
    fft512<true>(S + (t>>6)*LSTRIDE, t & 63, TW);
#pragma unroll
    for (int k=0;k<8;k++){
        int y = (t>>2) + (k<<6);
        int c = t & 3;
        d_field[ibase + (size_t)y*NN + x0 + c] = S[c*LSTRIDE + SK(y)];
    }
}

// P3/P5: row inverse FFT (unnormalized), * T_l, row forward FFT
__global__ void __launch_bounds__(256) mid_row(int l){
    __shared__ float2 S[4*LSTRIDE];
    __shared__ float2 TW[NN];
    int t = threadIdx.x;
    TW[t] = d_tw[t]; TW[t+256] = d_tw[t+256];
    int img  = blockIdx.x >> 7;
    int row0 = (blockIdx.x & 127) << 2;
    size_t ibase = (size_t)img*N2 + (size_t)row0*NN;
#pragma unroll
    for (int k=0;k<8;k++){
        int e = t + (k<<8);
        S[(e>>9)*LSTRIDE + SK(e & 511)] = d_field[ibase + e];
    }
    __syncthreads();
    fft512<true>(S + (t>>6)*LSTRIDE, t & 63, TW);
#pragma unroll
    for (int k=0;k<8;k++){
        int e = t + (k<<8);
        int si = (e>>9)*LSTRIDE + SK(e & 511);
        S[si] = cmul(S[si], d_Tl[l*N2 + row0*NN + e]);
    }
    __syncthreads();
    fft512<false>(S + (t>>6)*LSTRIDE, t & 63, TW);
#pragma unroll
    for (int k=0;k<8;k++){
        int e = t + (k<<8);
        d_field[ibase + e] = S[(e>>9)*LSTRIDE + SK(e & 511)];
    }
}

// P7: row inverse FFT (unnormalized; 1/N^2 already folded in), |.|^2
__global__ void __launch_bounds__(256) p7_row(){
    __shared__ float2 S[4*LSTRIDE];
    __shared__ float2 TW[NN];
    int t = threadIdx.x;
    TW[t] = d_tw[t]; TW[t+256] = d_tw[t+256];
    int img  = blockIdx.x >> 7;
    int row0 = (blockIdx.x & 127) << 2;
    size_t ibase = (size_t)img*N2 + (size_t)row0*NN;
#pragma unroll
    for (int k=0;k<8;k++){
        int e = t + (k<<8);
        S[(e>>9)*LSTRIDE + SK(e & 511)] = d_field[ibase + e];
    }
    __syncthreads();
    fft512<true>(S + (t>>6)*LSTRIDE, t & 63, TW);
#pragma unroll
    for (int k=0;k<8;k++){
        int e = t + (k<<8);
        float2 v = S[(e>>9)*LSTRIDE + SK(e & 511)];
        d_intens[ibase + e] = v.x*v.x + v.y*v.y;
    }
}

// reduction stage A: per (image, 4096-px chunk) -> 10 class partials (deterministic)
__global__ void __launch_bounds__(256) redA(){
    __shared__ float red[256*10];
    int t = threadIdx.x;
    int img = blockIdx.x >> 6;
    int ch  = blockIdx.x & 63;
    int p0  = ch << 12;
    float acc[10];
#pragma unroll
    for (int j=0;j<10;j++) acc[j] = 0.f;
    size_t ibase = (size_t)img*N2 + p0;
#pragma unroll
    for (int k=0;k<16;k++){
        int e = t + (k<<8);
        float v = d_intens[ibase + e];
        int c = d_cls[p0 + e];
#pragma unroll
        for (int j=0;j<10;j++) if (c==j) acc[j] += v;
    }
#pragma unroll
    for (int j=0;j<10;j++) red[t*10+j] = acc[j];
    __syncthreads();
    if (t < 10){
        float s = 0.f;
        for (int q=0;q<256;q++) s += red[q*10+t];
        d_part[blockIdx.x*10 + t] = s;
    }
}

// reduction stage B: sum over modes (9) and chunks (64), /9, write scores [16,10]
__global__ void redB(float* __restrict__ out){
    __shared__ float sh[64];
    int t = threadIdx.x;
    int b = blockIdx.x / 10, c = blockIdx.x % 10;
    float s = 0.f;
#pragma unroll
    for (int m=0;m<9;m++)
        s += d_part[(((m*16+b) << 6) + t)*10 + c];
    sh[t] = s; __syncthreads();
    for (int w=32; w>0; w>>=1){ if (t < w) sh[t] += sh[t+w]; __syncthreads(); }
    if (t==0) out[blockIdx.x] = sh[0] * (1.0f/9.0f);
}

// ---------------- launch ----------------
extern "C" void kernel_launch(void* const* d_in, const int* in_sizes, int n_in,
                              void* d_out, int out_size){
    const float* x_amp  = (const float*)d_in[0];
    const float* pnoise = (const float*)d_in[1];
    const float* amp    = (const float*)d_in[2];
    const float* phs    = (const float*)d_in[3];
    const float* mask   = (const float*)d_in[4];
    float* out = (float*)d_out;

    k_tw <<<1,   512>>>();
    k_H  <<<512, 512>>>();
    k_T  <<<3*512, 512>>>(amp, phs);
    k_cls<<<512, 512>>>(mask);

    p1_row  <<<NIMG*128, 256>>>(x_amp, pnoise);
    col_pass<<<NIMG*128, 256>>>(0);   // *H/N^2
    mid_row <<<NIMG*128, 256>>>(1);   // *T1
    col_pass<<<NIMG*128, 256>>>(0);   // *H/N^2
    mid_row <<<NIMG*128, 256>>>(2);   // *T2
    col_pass<<<NIMG*128, 256>>>(1);   // *H^2/N^2 (last two props fused)
    p7_row  <<<NIMG*128, 256>>>();

    redA<<<NIMG*64, 256>>>();
    redB<<<160, 64>>>(out);
}

// round 2
// speedup vs baseline: 1.5047x; 1.5047x over previous
#include <cuda_runtime.h>

#define PI_D 3.14159265358979323846
#define NN   512
#define N2   262144
#define NIMG 144
#define LSTRIDE 584
#define SK(i) ((i) + ((i)>>3))

// ---------------- device scratch (no allocations allowed) ----------------
static __device__ float2 d_field[(size_t)NIMG*N2];   // ~302 MB, in-place field
static __device__ float2 d_Tl[3*N2];                 // layer transmissions
static __device__ float2 d_Hb[N2];                   // H / N^2
static __device__ float2 d_Hb2[N2];                  // H^2 / N^2
static __device__ float2 d_tw[NN];                   // e^{-2pi i k/512}
static __device__ unsigned char d_cls[N2];           // pixel -> class (255 = none)
static __device__ float d_part[NIMG*128*10];         // per-block class partials

__device__ __forceinline__ float2 cmul(float2 a, float2 b){
    return make_float2(a.x*b.x - a.y*b.y, a.x*b.y + a.y*b.x);
}

// ---------------- radix-8 butterfly (DIF, output bit-reversed) ----------------
template<bool INV>
__device__ __forceinline__ void fft8(float2 v[8]){
    const float C0 = 0.70710678118654752440f;
    float2 t;
#define BTF(a,b) { t = a; a.x = t.x + b.x; a.y = t.y + b.y; b.x = t.x - b.x; b.y = t.y - b.y; }
    BTF(v[0],v[4]); BTF(v[1],v[5]); BTF(v[2],v[6]); BTF(v[3],v[7]);
    if (INV){
        v[5] = cmul(v[5], make_float2(C0,  C0));
        v[6] = make_float2(-v[6].y,  v[6].x);
        v[7] = cmul(v[7], make_float2(-C0, C0));
    } else {
        v[5] = cmul(v[5], make_float2(C0, -C0));
        v[6] = make_float2( v[6].y, -v[6].x);
        v[7] = cmul(v[7], make_float2(-C0,-C0));
    }
    BTF(v[0],v[2]); BTF(v[1],v[3]); BTF(v[4],v[6]); BTF(v[5],v[7]);
    if (INV){ v[3] = make_float2(-v[3].y, v[3].x); v[7] = make_float2(-v[7].y, v[7].x); }
    else    { v[3] = make_float2( v[3].y,-v[3].x); v[7] = make_float2( v[7].y,-v[7].x); }
    BTF(v[0],v[1]); BTF(v[2],v[3]); BTF(v[4],v[5]); BTF(v[6],v[7]);
#undef BTF
}

// ---------------- 512-pt FFT, register-direct ends, 2 smem exchanges --------
// Input:  v[r] = x[j + 64r]
// Output: element (j + 64r) is in v[brev[r]], brev = {0,4,2,6,1,5,3,7}
// Caller must guarantee s[] is safe to overwrite at entry, and that a sync
// separates this call's trailing loads from any later overwrite of s[].
template<bool INV>
__device__ __forceinline__ void fft512_reg(float2 v[8], float2* s, int j,
                                           const float2* tw){
    const int brev[8] = {0,4,2,6,1,5,3,7};
    // stage 0: Ns=1, no twiddles
    fft8<INV>(v);
#pragma unroll
    for (int r=0;r<8;r++) s[SK(8*j + r)] = v[brev[r]];
    __syncthreads();
    // stage 1: Ns=8
#pragma unroll
    for (int r=0;r<8;r++) v[r] = s[SK(j + 64*r)];
    int jm = j & 7;
#pragma unroll
    for (int r=1;r<8;r++){
        float2 w = tw[r*jm*8];
        if (INV) w.y = -w.y;
        v[r] = cmul(v[r], w);
    }
    fft8<INV>(v);
    int idxD = ((j - jm) << 3) + jm;
    __syncthreads();
#pragma unroll
    for (int r=0;r<8;r++) s[SK(idxD + 8*r)] = v[brev[r]];
    __syncthreads();
    // stage 2: Ns=64
#pragma unroll
    for (int r=0;r<8;r++) v[r] = s[SK(j + 64*r)];
#pragma unroll
    for (int r=1;r<8;r++){
        float2 w = tw[r*j];
        if (INV) w.y = -w.y;
        v[r] = cmul(v[r], w);
    }
    fft8<INV>(v);
}

// ---------------- init kernels ----------------
__global__ void k_tw(){
    int t = threadIdx.x;
    double ang = -2.0*PI_D*(double)t/512.0;
    d_tw[t] = make_float2((float)cos(ang), (float)sin(ang));
}

__global__ void k_init(const float* __restrict__ amp, const float* __restrict__ phs,
                       const float* __restrict__ mask){
    int i = blockIdx.x, j = threadIdx.x;
    int idx = i*NN + j;
    // --- transfer function H, H^2 (with 1/N^2 folded in) ---
    float inv = 1.0f/(512.0f*8e-6f);
    float fx = (float)(i<256 ? i : i-512) * inv;
    float fy = (float)(j<256 ? j : j-512) * inv;
    const float lam = 5.32e-7f;
    float lx = lam*fx, ly = lam*fy;
    float arg = 1.0f - lx*lx - ly*ly;
    float sa = sqrtf(fmaxf(arg, 0.0f));
    const float KZ = (float)(2.0*PI_D/5.32e-7*0.05);
    float phi = KZ * sa;                   // f32 rounding, matches jax path
    double s, c;
    sincos((double)phi, &s, &c);           // accurate for huge args
    float hr = (float)c, hi = (float)s;
    const float sc = 1.0f/262144.0f;
    d_Hb [idx] = make_float2(hr*sc, hi*sc);
    d_Hb2[idx] = make_float2((hr*hr - hi*hi)*sc, 2.0f*hr*hi*sc);
    // --- layer transmissions ---
#pragma unroll
    for (int l=0;l<3;l++){
        float a = amp[l*N2+idx], p = phs[l*N2+idx];
        float sn, cs; sincosf(p, &sn, &cs);
        d_Tl[l*N2+idx] = make_float2(a*cs, a*sn);
    }
    // --- detector class map ---
    unsigned char cl = 255;
#pragma unroll
    for (int q=0;q<10;q++) if (mask[q*N2 + idx] > 0.5f) cl = (unsigned char)q;
    d_cls[idx] = cl;
}

// ---------------- pass kernels ----------------
// P1: build E0*T0 in registers, row forward FFT
__global__ void __launch_bounds__(256) p1_row(const float* __restrict__ xamp,
                                              const float* __restrict__ pn){
    __shared__ float2 S[4*LSTRIDE];
    __shared__ float2 TW[NN];
    int t = threadIdx.x;
    TW[t] = d_tw[t]; TW[t+256] = d_tw[t+256];
    int line = t >> 6, j = t & 63;
    int img  = blockIdx.x >> 7;
    int row  = ((blockIdx.x & 127) << 2) + line;
    int b = img & 15, m = img >> 4;
    float fm = 0.5f * (float)(m+1);
    size_t ibase = (size_t)img*N2 + (size_t)row*NN;
    size_t bbase = (size_t)b  *N2 + (size_t)row*NN;
    float2 v[8];
#pragma unroll
    for (int r=0;r<8;r++){
        int e = j + 64*r;
        float p  = pn  [ibase + e];
        float xa = xamp[bbase + e];
        float sn, cs; __sincosf(p*fm, &sn, &cs);
        float2 ein = make_float2(xa*cs, xa*sn);
        v[r] = cmul(ein, d_Tl[row*NN + e]);
    }
    __syncthreads();   // TW visible; S free
    fft512_reg<false>(v, S + line*LSTRIDE, j, TW);
    const int brev[8] = {0,4,2,6,1,5,3,7};
#pragma unroll
    for (int r=0;r<8;r++) d_field[ibase + j + 64*r] = v[brev[r]];
}

// P2/P4/P6: col fwd FFT, * H (or H^2, incl 1/N^2), col inverse FFT
__global__ void __launch_bounds__(256) col_pass(int h2){
    __shared__ float2 S[4*LSTRIDE];
    __shared__ float2 TW[NN];
    int t = threadIdx.x;
    TW[t] = d_tw[t]; TW[t+256] = d_tw[t+256];
    int c = t & 3, j = t >> 2;
    int img = blockIdx.x >> 7;
    int col = ((blockIdx.x & 127) << 2) + c;
    size_t ibase = (size_t)img*N2;
    const int brev[8] = {0,4,2,6,1,5,3,7};
    float2 v[8];
#pragma unroll
    for (int r=0;r<8;r++)
        v[r] = d_field[ibase + (size_t)(j + 64*r)*NN + col];
    __syncthreads();
    fft512_reg<false>(v, S + c*LSTRIDE, j, TW);
    const float2* __restrict__ Hm = h2 ? d_Hb2 : d_Hb;
    float2 u[8];
#pragma unroll
    for (int r=0;r<8;r++)
        u[r] = cmul(v[brev[r]], Hm[(j + 64*r)*NN + col]);
    __syncthreads();   // S free for second FFT
    fft512_reg<true>(u, S + c*LSTRIDE, j, TW);
#pragma unroll
    for (int r=0;r<8;r++)
        d_field[ibase + (size_t)(j + 64*r)*NN + col] = u[brev[r]];
}

// P3/P5: row inverse FFT (unnormalized), * T_l, row forward FFT
__global__ void __launch_bounds__(256) mid_row(int l){
    __shared__ float2 S[4*LSTRIDE];
    __shared__ float2 TW[NN];
    int t = threadIdx.x;
    TW[t] = d_tw[t]; TW[t+256] = d_tw[t+256];
    int line = t >> 6, j = t & 63;
    int img  = blockIdx.x >> 7;
    int row  = ((blockIdx.x & 127) << 2) + line;
    size_t ibase = (size_t)img*N2 + (size_t)row*NN;
    const int brev[8] = {0,4,2,6,1,5,3,7};
    float2 v[8];
#pragma unroll
    for (int r=0;r<8;r++) v[r] = d_field[ibase + j + 64*r];
    __syncthreads();
    fft512_reg<true>(v, S + line*LSTRIDE, j, TW);
    float2 u[8];
#pragma unroll
    for (int r=0;r<8;r++)
        u[r] = cmul(v[brev[r]], d_Tl[l*N2 + row*NN + j + 64*r]);
    __syncthreads();
    fft512_reg<false>(u, S + line*LSTRIDE, j, TW);
#pragma unroll
    for (int r=0;r<8;r++) d_field[ibase + j + 64*r] = u[brev[r]];
}

// P7: row inverse FFT, |.|^2, in-block class binning (deterministic)
__global__ void __launch_bounds__(256) p7_row(){
    __shared__ float2 S[4*LSTRIDE];
    __shared__ float2 TW[NN];
    __shared__ float WP[8][10];
    int t = threadIdx.x;
    TW[t] = d_tw[t]; TW[t+256] = d_tw[t+256];
    int line = t >> 6, j = t & 63;
    int img  = blockIdx.x >> 7;
    int row  = ((blockIdx.x & 127) << 2) + line;
    size_t ibase = (size_t)img*N2 + (size_t)row*NN;
    const int brev[8] = {0,4,2,6,1,5,3,7};
    float2 v[8];
#pragma unroll
    for (int r=0;r<8;r++) v[r] = d_field[ibase + j + 64*r];
    __syncthreads();
    fft512_reg<true>(v, S + line*LSTRIDE, j, TW);

    float acc[10];
#pragma unroll
    for (int q=0;q<10;q++) acc[q] = 0.f;
#pragma unroll
    for (int r=0;r<8;r++){
        float2 f = v[brev[r]];
        float I = f.x*f.x + f.y*f.y;
        int cl = d_cls[row*NN + j + 64*r];
#pragma unroll
        for (int q=0;q<10;q++) if (cl==q) acc[q] += I;
    }
    // warp reduce each class
#pragma unroll
    for (int q=0;q<10;q++){
#pragma unroll
        for (int o=16;o>0;o>>=1)
            acc[q] += __shfl_xor_sync(0xffffffffu, acc[q], o);
    }
    int w = t >> 5;
    if ((t & 31) == 0){
#pragma unroll
        for (int q=0;q<10;q++) WP[w][q] = acc[q];
    }
    __syncthreads();
    if (t < 10){
        float s = 0.f;
#pragma unroll
        for (int q=0;q<8;q++) s += WP[q][t];
        d_part[blockIdx.x*10 + t] = s;
    }
}

// final: sum over 9 modes x 128 blocks, /9, scores [16,10]
__global__ void redB(float* __restrict__ out){
    __shared__ float sh[128];
    int t = threadIdx.x;
    int b = blockIdx.x / 10, c = blockIdx.x % 10;
    float s = 0.f;
#pragma unroll
    for (int m=0;m<9;m++)
        s += d_part[(((m*16+b) << 7) + t)*10 + c];
    sh[t] = s; __syncthreads();
    for (int w=64; w>0; w>>=1){ if (t < w) sh[t] += sh[t+w]; __syncthreads(); }
    if (t==0) out[blockIdx.x] = sh[0] * (1.0f/9.0f);
}

// ---------------- launch ----------------
extern "C" void kernel_launch(void* const* d_in, const int* in_sizes, int n_in,
                              void* d_out, int out_size){
    const float* x_amp  = (const float*)d_in[0];
    const float* pnoise = (const float*)d_in[1];
    const float* amp    = (const float*)d_in[2];
    const float* phs    = (const float*)d_in[3];
    const float* mask   = (const float*)d_in[4];
    float* out = (float*)d_out;

    k_tw  <<<1,   512>>>();
    k_init<<<512, 512>>>(amp, phs, mask);

    p1_row  <<<NIMG*128, 256>>>(x_amp, pnoise);
    col_pass<<<NIMG*128, 256>>>(0);   // *H/N^2
    mid_row <<<NIMG*128, 256>>>(1);   // *T1
    col_pass<<<NIMG*128, 256>>>(0);   // *H/N^2
    mid_row <<<NIMG*128, 256>>>(2);   // *T2
    col_pass<<<NIMG*128, 256>>>(1);   // *H^2/N^2 (last two props fused)
    p7_row  <<<NIMG*128, 256>>>();

    redB<<<160, 128>>>(out);
}

// round 3
// speedup vs baseline: 1.7148x; 1.1397x over previous
#include <cuda_runtime.h>

#define PI_D 3.14159265358979323846
#define NN   512
#define N2   262144
#define NIMG 144
#define RSTRIDE 584   // row kernels: warp stays within one region -> stride free
#define CSTRIDE 578   // col kernels: 2*578*2p mod 32 = 8p -> conflict-free across regions
#define SK(i) ((i) + ((i)>>3))

// ---------------- device scratch (no allocations allowed) ----------------
static __device__ float2 d_field[(size_t)NIMG*N2];   // ~302 MB, in-place field
static __device__ float2 d_Tl[3*N2];                 // layer transmissions
static __device__ float2 d_Hb[N2];                   // H / N^2
static __device__ float2 d_Hb2[N2];                  // H^2 / N^2
static __device__ float2 d_tw[NN];                   // e^{-2pi i k/512}
static __device__ unsigned char d_cls[N2];           // pixel -> class (255 = none)
static __device__ float d_part[NIMG*64*10];          // per-block class partials

__device__ __forceinline__ float2 cmul(float2 a, float2 b){
    return make_float2(a.x*b.x - a.y*b.y, a.x*b.y + a.y*b.x);
}

// ---------------- radix-8 butterfly (DIF, output bit-reversed) ----------------
template<bool INV>
__device__ __forceinline__ void fft8(float2 v[8]){
    const float C0 = 0.70710678118654752440f;
    float2 t;
#define BTF(a,b) { t = a; a.x = t.x + b.x; a.y = t.y + b.y; b.x = t.x - b.x; b.y = t.y - b.y; }
    BTF(v[0],v[4]); BTF(v[1],v[5]); BTF(v[2],v[6]); BTF(v[3],v[7]);
    if (INV){
        v[5] = cmul(v[5], make_float2(C0,  C0));
        v[6] = make_float2(-v[6].y,  v[6].x);
        v[7] = cmul(v[7], make_float2(-C0, C0));
    } else {
        v[5] = cmul(v[5], make_float2(C0, -C0));
        v[6] = make_float2( v[6].y, -v[6].x);
        v[7] = cmul(v[7], make_float2(-C0,-C0));
    }
    BTF(v[0],v[2]); BTF(v[1],v[3]); BTF(v[4],v[6]); BTF(v[5],v[7]);
    if (INV){ v[3] = make_float2(-v[3].y, v[3].x); v[7] = make_float2(-v[7].y, v[7].x); }
    else    { v[3] = make_float2( v[3].y,-v[3].x); v[7] = make_float2( v[7].y,-v[7].x); }
    BTF(v[0],v[1]); BTF(v[2],v[3]); BTF(v[4],v[5]); BTF(v[6],v[7]);
#undef BTF
}

// ---- dual-slot 512-pt FFT, ONE line, thread owns slots j and j+32 (j in 0..31)
// Input:  v[r] = x[j+64r], w[r] = x[j+32+64r]
// Output: element (j+64r) in v[brev[r]], (j+32+64r) in w[brev[r]]
template<bool INV>
__device__ __forceinline__ void fft512_dual(float2 v[8], float2 w[8],
                                            float2* s, int j, const float2* tw){
    const int brev[8] = {0,4,2,6,1,5,3,7};
    fft8<INV>(v); fft8<INV>(w);
#pragma unroll
    for (int r=0;r<8;r++){ s[SK(8*j+r)] = v[brev[r]]; s[SK(8*(j+32)+r)] = w[brev[r]]; }
    __syncthreads();
#pragma unroll
    for (int r=0;r<8;r++){ v[r] = s[SK(j+64*r)]; w[r] = s[SK(j+32+64*r)]; }
    int jm = j & 7;
#pragma unroll
    for (int r=1;r<8;r++){
        float2 q = tw[r*jm*8];
        if (INV) q.y = -q.y;
        v[r] = cmul(v[r], q); w[r] = cmul(w[r], q);   // (j+32)&7 == j&7
    }
    fft8<INV>(v); fft8<INV>(w);
    int iv = ((j - jm) << 3) + jm;
    int iw = iv + 256;
    __syncthreads();
#pragma unroll
    for (int r=0;r<8;r++){ s[SK(iv + 8*r)] = v[brev[r]]; s[SK(iw + 8*r)] = w[brev[r]]; }
    __syncthreads();
#pragma unroll
    for (int r=0;r<8;r++){ v[r] = s[SK(j+64*r)]; w[r] = s[SK(j+32+64*r)]; }
#pragma unroll
    for (int r=1;r<8;r++){
        float2 qv = tw[r*j], qw = tw[r*(j+32)];
        if (INV){ qv.y = -qv.y; qw.y = -qw.y; }
        v[r] = cmul(v[r], qv); w[r] = cmul(w[r], qw);
    }
    fft8<INV>(v); fft8<INV>(w);
}

// ---- dual-line 512-pt FFT: TWO independent lines (regions sA, sB), same slot j (0..63)
template<bool INV>
__device__ __forceinline__ void fft512_dual2(float2 v[8], float2 w[8],
                                             float2* sA, float2* sB, int j,
                                             const float2* tw){
    const int brev[8] = {0,4,2,6,1,5,3,7};
    fft8<INV>(v); fft8<INV>(w);
#pragma unroll
    for (int r=0;r<8;r++){ sA[SK(8*j+r)] = v[brev[r]]; sB[SK(8*j+r)] = w[brev[r]]; }
    __syncthreads();
#pragma unroll
    for (int r=0;r<8;r++){ v[r] = sA[SK(j+64*r)]; w[r] = sB[SK(j+64*r)]; }
    int jm = j & 7;
#pragma unroll
    for (int r=1;r<8;r++){
        float2 q = tw[r*jm*8];
        if (INV) q.y = -q.y;
        v[r] = cmul(v[r], q); w[r] = cmul(w[r], q);
    }
    fft8<INV>(v); fft8<INV>(w);
    int idxD = ((j - jm) << 3) + jm;
    __syncthreads();
#pragma unroll
    for (int r=0;r<8;r++){ sA[SK(idxD + 8*r)] = v[brev[r]]; sB[SK(idxD + 8*r)] = w[brev[r]]; }
    __syncthreads();
#pragma unroll
    for (int r=0;r<8;r++){ v[r] = sA[SK(j+64*r)]; w[r] = sB[SK(j+64*r)]; }
#pragma unroll
    for (int r=1;r<8;r++){
        float2 q = tw[r*j];
        if (INV) q.y = -q.y;
        v[r] = cmul(v[r], q); w[r] = cmul(w[r], q);
    }
    fft8<INV>(v); fft8<INV>(w);
}

// ---------------- init kernels ----------------
__global__ void k_tw(){
    int t = threadIdx.x;
    double ang = -2.0*PI_D*(double)t/512.0;
    d_tw[t] = make_float2((float)cos(ang), (float)sin(ang));
}

__global__ void k_init(const float* __restrict__ amp, const float* __restrict__ phs,
                       const float* __restrict__ mask){
    int i = blockIdx.x, j = threadIdx.x;
    int idx = i*NN + j;
    float inv = 1.0f/(512.0f*8e-6f);
    float fx = (float)(i<256 ? i : i-512) * inv;
    float fy = (float)(j<256 ? j : j-512) * inv;
    const float lam = 5.32e-7f;
    float lx = lam*fx, ly = lam*fy;
    float arg = 1.0f - lx*lx - ly*ly;
    float sa = sqrtf(fmaxf(arg, 0.0f));
    const float KZ = (float)(2.0*PI_D/5.32e-7*0.05);
    float phi = KZ * sa;                   // f32 rounding, matches jax path
    double s, c;
    sincos((double)phi, &s, &c);           // accurate for huge args
    float hr = (float)c, hi = (float)s;
    const float sc = 1.0f/262144.0f;
    d_Hb [idx] = make_float2(hr*sc, hi*sc);
    d_Hb2[idx] = make_float2((hr*hr - hi*hi)*sc, 2.0f*hr*hi*sc);
#pragma unroll
    for (int l=0;l<3;l++){
        float a = amp[l*N2+idx], p = phs[l*N2+idx];
        float sn, cs; sincosf(p, &sn, &cs);
        d_Tl[l*N2+idx] = make_float2(a*cs, a*sn);
    }
    unsigned char cl = 255;
#pragma unroll
    for (int q=0;q<10;q++) if (mask[q*N2 + idx] > 0.5f) cl = (unsigned char)q;
    d_cls[idx] = cl;
}

// ---------------- pass kernels ----------------
// Row kernels: 8 rows per 256-thread block; warp = one row; thread = slots j, j+32.

// P1: build E0*T0 in registers, row forward FFT
__global__ void __launch_bounds__(256) p1_row(const float* __restrict__ xamp,
                                              const float* __restrict__ pn, int img0){
    __shared__ float2 S[8*RSTRIDE];
    __shared__ float2 TW[NN];
    int t = threadIdx.x;
    TW[t] = d_tw[t]; TW[t+256] = d_tw[t+256];
    int line = t >> 5, j = t & 31;
    int img  = img0 + (blockIdx.x >> 6);
    int row  = ((blockIdx.x & 63) << 3) + line;
    int b = img & 15, m = img >> 4;
    float fm = 0.5f * (float)(m+1);
    size_t ibase = (size_t)img*N2 + (size_t)row*NN;
    size_t bbase = (size_t)b  *N2 + (size_t)row*NN;
    float2 v[8], w[8];
#pragma unroll
    for (int r=0;r<8;r++){
        int e1 = j + 64*r, e2 = j + 32 + 64*r;
        float p1v = pn[ibase + e1], p2v = pn[ibase + e2];
        float x1 = xamp[bbase + e1], x2 = xamp[bbase + e2];
        float sn, cs;
        __sincosf(p1v*fm, &sn, &cs);
        float2 a = make_float2(x1*cs, x1*sn);
        v[r] = cmul(a, d_Tl[row*NN + e1]);
        __sincosf(p2v*fm, &sn, &cs);
        float2 bb = make_float2(x2*cs, x2*sn);
        w[r] = cmul(bb, d_Tl[row*NN + e2]);
    }
    fft512_dual<false>(v, w, S + line*RSTRIDE, j, TW);
    const int brev[8] = {0,4,2,6,1,5,3,7};
#pragma unroll
    for (int r=0;r<8;r++){
        d_field[ibase + j + 64*r]      = v[brev[r]];
        d_field[ibase + j + 32 + 64*r] = w[brev[r]];
    }
}

// col pass: 8 columns per 256-thread block (thread owns adjacent col pair via float4)
__global__ void __launch_bounds__(256) col_pass(int h2, int img0){
    __shared__ float2 S[8*CSTRIDE];
    __shared__ float2 TW[NN];
    int t = threadIdx.x;
    TW[t] = d_tw[t]; TW[t+256] = d_tw[t+256];
    int p = t & 3, j = t >> 2;          // pair id, slot
    int img = img0 + (blockIdx.x >> 6);
    int colA = ((blockIdx.x & 63) << 3) + 2*p;
    size_t ibase = (size_t)img*N2;
    const int brev[8] = {0,4,2,6,1,5,3,7};
    float2 v[8], w[8];
#pragma unroll
    for (int r=0;r<8;r++){
        float4 F = *(const float4*)&d_field[ibase + (size_t)(j+64*r)*NN + colA];
        v[r] = make_float2(F.x, F.y);
        w[r] = make_float2(F.z, F.w);
    }
    float2* sA = S + (2*p  )*CSTRIDE;
    float2* sB = S + (2*p+1)*CSTRIDE;
    fft512_dual2<false>(v, w, sA, sB, j, TW);
    const float2* __restrict__ Hm = h2 ? d_Hb2 : d_Hb;
    float2 u[8], uw[8];
#pragma unroll
    for (int r=0;r<8;r++){
        float4 Hp = *(const float4*)&Hm[(j+64*r)*NN + colA];
        u [r] = cmul(v[brev[r]], make_float2(Hp.x, Hp.y));
        uw[r] = cmul(w[brev[r]], make_float2(Hp.z, Hp.w));
    }
    __syncthreads();    // S free for second FFT
    fft512_dual2<true>(u, uw, sA, sB, j, TW);
#pragma unroll
    for (int r=0;r<8;r++){
        float4 F;
        F.x = u[brev[r]].x;  F.y = u[brev[r]].y;
        F.z = uw[brev[r]].x; F.w = uw[brev[r]].y;
        *(float4*)&d_field[ibase + (size_t)(j+64*r)*NN + colA] = F;
    }
}

// P3/P5: row inverse FFT (unnormalized), * T_l, row forward FFT
__global__ void __launch_bounds__(256) mid_row(int l, int img0){
    __shared__ float2 S[8*RSTRIDE];
    __shared__ float2 TW[NN];
    int t = threadIdx.x;
    TW[t] = d_tw[t]; TW[t+256] = d_tw[t+256];
    int line = t >> 5, j = t & 31;
    int img  = img0 + (blockIdx.x >> 6);
    int row  = ((blockIdx.x & 63) << 3) + line;
    size_t ibase = (size_t)img*N2 + (size_t)row*NN;
    const int brev[8] = {0,4,2,6,1,5,3,7};
    float2 v[8], w[8];
#pragma unroll
    for (int r=0;r<8;r++){
        v[r] = d_field[ibase + j + 64*r];
        w[r] = d_field[ibase + j + 32 + 64*r];
    }
    float2* s = S + line*RSTRIDE;
    fft512_dual<true>(v, w, s, j, TW);
    const float2* __restrict__ T = d_Tl + l*N2 + row*NN;
    float2 u[8], uw[8];
#pragma unroll
    for (int r=0;r<8;r++){
        u [r] = cmul(v[brev[r]], T[j + 64*r]);
        uw[r] = cmul(w[brev[r]], T[j + 32 + 64*r]);
    }
    __syncthreads();
    fft512_dual<false>(u, uw, s, j, TW);
#pragma unroll
    for (int r=0;r<8;r++){
        d_field[ibase + j + 64*r]      = u[brev[r]];
        d_field[ibase + j + 32 + 64*r] = uw[brev[r]];
    }
}

// P7: row inverse FFT, |.|^2, in-block class binning (deterministic)
__global__ void __launch_bounds__(256) p7_row(int img0){
    __shared__ float2 S[8*RSTRIDE];
    __shared__ float2 TW[NN];
    __shared__ float WP[8][10];
    int t = threadIdx.x;
    TW[t] = d_tw[t]; TW[t+256] = d_tw[t+256];
    int line = t >> 5, j = t & 31;
    int img  = img0 + (blockIdx.x >> 6);
    int chunk = blockIdx.x & 63;
    int row  = (chunk << 3) + line;
    size_t ibase = (size_t)img*N2 + (size_t)row*NN;
    const int brev[8] = {0,4,2,6,1,5,3,7};
    float2 v[8], w[8];
#pragma unroll
    for (int r=0;r<8;r++){
        v[r] = d_field[ibase + j + 64*r];
        w[r] = d_field[ibase + j + 32 + 64*r];
    }
    fft512_dual<true>(v, w, S + line*RSTRIDE, j, TW);

    float acc[10];
#pragma unroll
    for (int q=0;q<10;q++) acc[q] = 0.f;
#pragma unroll
    for (int r=0;r<8;r++){
        float2 f = v[brev[r]];
        float I = f.x*f.x + f.y*f.y;
        int cl = d_cls[row*NN + j + 64*r];
#pragma unroll
        for (int q=0;q<10;q++) if (cl==q) acc[q] += I;
        f = w[brev[r]];
        I = f.x*f.x + f.y*f.y;
        cl = d_cls[row*NN + j + 32 + 64*r];
#pragma unroll
        for (int q=0;q<10;q++) if (cl==q) acc[q] += I;
    }
#pragma unroll
    for (int q=0;q<10;q++){
#pragma unroll
        for (int o=16;o>0;o>>=1)
            acc[q] += __shfl_xor_sync(0xffffffffu, acc[q], o);
    }
    if (j == 0){
#pragma unroll
        for (int q=0;q<10;q++) WP[line][q] = acc[q];
    }
    __syncthreads();
    if (t < 10){
        float s = 0.f;
#pragma unroll
        for (int q=0;q<8;q++) s += WP[q][t];
        d_part[(img*64 + chunk)*10 + t] = s;
    }
}

// final: sum over 9 modes x 64 chunks, /9, scores [16,10]
__global__ void redB(float* __restrict__ out){
    __shared__ float sh[64];
    int t = threadIdx.x;
    int b = blockIdx.x / 10, c = blockIdx.x % 10;
    float s = 0.f;
#pragma unroll
    for (int m=0;m<9;m++)
        s += d_part[(((m*16+b) << 6) + t)*10 + c];
    sh[t] = s; __syncthreads();
    for (int w=32; w>0; w>>=1){ if (t < w) sh[t] += sh[t+w]; __syncthreads(); }
    if (t==0) out[blockIdx.x] = sh[0] * (1.0f/9.0f);
}

// ---------------- launch ----------------
extern "C" void kernel_launch(void* const* d_in, const int* in_sizes, int n_in,
                              void* d_out, int out_size){
    const float* x_amp  = (const float*)d_in[0];
    const float* pnoise = (const float*)d_in[1];
    const float* amp    = (const float*)d_in[2];
    const float* phs    = (const float*)d_in[3];
    const float* mask   = (const float*)d_in[4];
    float* out = (float*)d_out;

    k_tw  <<<1,   512>>>();
    k_init<<<512, 512>>>(amp, phs, mask);

    const int G = 36;                       // 36 img * 2MB = 72MB, fits L2
    for (int g = 0; g < NIMG/G; g++){
        int i0 = g*G;
        p1_row  <<<G*64, 256>>>(x_amp, pnoise, i0);
        col_pass<<<G*64, 256>>>(0, i0);     // *H/N^2
        mid_row <<<G*64, 256>>>(1, i0);     // *T1
        col_pass<<<G*64, 256>>>(0, i0);     // *H/N^2
        mid_row <<<G*64, 256>>>(2, i0);     // *T2
        col_pass<<<G*64, 256>>>(1, i0);     // *H^2/N^2 (last two props fused)
        p7_row  <<<G*64, 256>>>(i0);
    }
    redB<<<160, 64>>>(out);
}

// round 6
// speedup vs baseline: 1.7289x; 1.0082x over previous
#include <cuda_runtime.h>

#define PI_D 3.14159265358979323846
#define NN   512
#define N2   262144
#define NIMG 144
#define RSTRIDE 584   // row kernels: warp stays within one region -> stride free
#define CSTRIDE 578   // col kernels: 2*578*2p mod 32 = 8p -> conflict-free across regions
#define SK(i) ((i) + ((i)>>3))

// ---------------- device scratch (no allocations allowed) ----------------
static __device__ float2 d_field[(size_t)NIMG*N2];   // ~302 MB, in-place field
static __device__ float2 d_Tl[3*N2];                 // layer transmissions
static __device__ float2 d_Hb[N2];                   // H / N^2
static __device__ float2 d_Hb2[N2];                  // H^2 / N^2
static __device__ float2 d_tw[NN];                   // e^{-2pi i k/512}
static __device__ unsigned char d_cls[N2];           // pixel -> class (255 = none)
static __device__ float d_part[NIMG*64*10];          // per-block class partials

__device__ __forceinline__ float2 cmul(float2 a, float2 b){
    return make_float2(a.x*b.x - a.y*b.y, a.x*b.y + a.y*b.x);
}

#define BREV_DECL const int brev[8] = {0,4,2,6,1,5,3,7}

// ---------------- radix-8 butterfly (DIF, output bit-reversed) ----------------
template<bool INV>
__device__ __forceinline__ void fft8(float2 v[8]){
    const float C0 = 0.70710678118654752440f;
    float2 t;
#define BTF(a,b) { t = a; a.x = t.x + b.x; a.y = t.y + b.y; b.x = t.x - b.x; b.y = t.y - b.y; }
    BTF(v[0],v[4]); BTF(v[1],v[5]); BTF(v[2],v[6]); BTF(v[3],v[7]);
    if (INV){
        v[5] = cmul(v[5], make_float2(C0,  C0));
        v[6] = make_float2(-v[6].y,  v[6].x);
        v[7] = cmul(v[7], make_float2(-C0, C0));
    } else {
        v[5] = cmul(v[5], make_float2(C0, -C0));
        v[6] = make_float2( v[6].y, -v[6].x);
        v[7] = cmul(v[7], make_float2(-C0,-C0));
    }
    BTF(v[0],v[2]); BTF(v[1],v[3]); BTF(v[4],v[6]); BTF(v[5],v[7]);
    if (INV){ v[3] = make_float2(-v[3].y, v[3].x); v[7] = make_float2(-v[7].y, v[7].x); }
    else    { v[3] = make_float2( v[3].y,-v[3].x); v[7] = make_float2( v[7].y,-v[7].x); }
    BTF(v[0],v[1]); BTF(v[2],v[3]); BTF(v[4],v[5]); BTF(v[6],v[7]);
#undef BTF
}

// apply brev permutation in registers (pure renaming, elided by ptxas)
__device__ __forceinline__ void permute_brev(float2 v[8]){
    BREV_DECL;
    float2 t[8];
#pragma unroll
    for (int r=0;r<8;r++) t[r] = v[brev[r]];
#pragma unroll
    for (int r=0;r<8;r++) v[r] = t[r];
}

// ---- dual-slot 512-pt FFT, ONE line, thread owns slots j and j+32 (j in 0..31)
// PERM=false: input v[r] = x[j+64r], w[r] = x[j+32+64r]
// PERM=true:  input v[brev[r]] = x[j+64r]  (i.e. output layout of a previous call)
// Output: element (j+64r) in v[brev[r]], (j+32+64r) in w[brev[r]]
template<bool INV, bool PERM>
__device__ __forceinline__ void fft512_dual(float2 v[8], float2 w[8],
                                            float2* s, int j, const float2* tw){
    BREV_DECL;
    if (PERM){ permute_brev(v); permute_brev(w); }
    fft8<INV>(v); fft8<INV>(w);
#pragma unroll
    for (int r=0;r<8;r++){ s[SK(8*j+r)] = v[brev[r]]; s[SK(8*(j+32)+r)] = w[brev[r]]; }
    __syncthreads();
#pragma unroll
    for (int r=0;r<8;r++){ v[r] = s[SK(j+64*r)]; w[r] = s[SK(j+32+64*r)]; }
    int jm = j & 7;
#pragma unroll
    for (int r=1;r<8;r++){
        float2 q = tw[r*jm*8];
        if (INV) q.y = -q.y;
        v[r] = cmul(v[r], q); w[r] = cmul(w[r], q);   // (j+32)&7 == j&7
    }
    fft8<INV>(v); fft8<INV>(w);
    int iv = ((j - jm) << 3) + jm;
    int iw = iv + 256;
    __syncthreads();
#pragma unroll
    for (int r=0;r<8;r++){ s[SK(iv + 8*r)] = v[brev[r]]; s[SK(iw + 8*r)] = w[brev[r]]; }
    __syncthreads();
#pragma unroll
    for (int r=0;r<8;r++){ v[r] = s[SK(j+64*r)]; w[r] = s[SK(j+32+64*r)]; }
#pragma unroll
    for (int r=1;r<8;r++){
        float2 qv = tw[r*j], qw = tw[r*(j+32)];
        if (INV){ qv.y = -qv.y; qw.y = -qw.y; }
        v[r] = cmul(v[r], qv); w[r] = cmul(w[r], qw);
    }
    fft8<INV>(v); fft8<INV>(w);
}

// ---- dual-line 512-pt FFT: TWO independent lines (regions sA, sB), same slot j (0..63)
template<bool INV, bool PERM>
__device__ __forceinline__ void fft512_dual2(float2 v[8], float2 w[8],
                                             float2* sA, float2* sB, int j,
                                             const float2* tw){
    BREV_DECL;
    if (PERM){ permute_brev(v); permute_brev(w); }
    fft8<INV>(v); fft8<INV>(w);
#pragma unroll
    for (int r=0;r<8;r++){ sA[SK(8*j+r)] = v[brev[r]]; sB[SK(8*j+r)] = w[brev[r]]; }
    __syncthreads();
#pragma unroll
    for (int r=0;r<8;r++){ v[r] = sA[SK(j+64*r)]; w[r] = sB[SK(j+64*r)]; }
    int jm = j & 7;
#pragma unroll
    for (int r=1;r<8;r++){
        float2 q = tw[r*jm*8];
        if (INV) q.y = -q.y;
        v[r] = cmul(v[r], q); w[r] = cmul(w[r], q);
    }
    fft8<INV>(v); fft8<INV>(w);
    int idxD = ((j - jm) << 3) + jm;
    __syncthreads();
#pragma unroll
    for (int r=0;r<8;r++){ sA[SK(idxD + 8*r)] = v[brev[r]]; sB[SK(idxD + 8*r)] = w[brev[r]]; }
    __syncthreads();
#pragma unroll
    for (int r=0;r<8;r++){ v[r] = sA[SK(j+64*r)]; w[r] = sB[SK(j+64*r)]; }
#pragma unroll
    for (int r=1;r<8;r++){
        float2 q = tw[r*j];
        if (INV) q.y = -q.y;
        v[r] = cmul(v[r], q); w[r] = cmul(w[r], q);
    }
    fft8<INV>(v); fft8<INV>(w);
}

// ---------------- init kernels ----------------
__global__ void k_tw(){
    int t = threadIdx.x;
    double ang = -2.0*PI_D*(double)t/512.0;
    d_tw[t] = make_float2((float)cos(ang), (float)sin(ang));
}

__global__ void k_init(const float* __restrict__ amp, const float* __restrict__ phs,
                       const float* __restrict__ mask){
    int i = blockIdx.x, j = threadIdx.x;
    int idx = i*NN + j;
    float inv = 1.0f/(512.0f*8e-6f);
    float fx = (float)(i<256 ? i : i-512) * inv;
    float fy = (float)(j<256 ? j : j-512) * inv;
    const float lam = 5.32e-7f;
    float lx = lam*fx, ly = lam*fy;
    float arg = 1.0f - lx*lx - ly*ly;
    float sa = sqrtf(fmaxf(arg, 0.0f));
    const float KZ = (float)(2.0*PI_D/5.32e-7*0.05);
    float phi = KZ * sa;                   // f32 rounding, matches jax path
    double s, c;
    sincos((double)phi, &s, &c);           // accurate for huge args
    float hr = (float)c, hi = (float)s;
    const float sc = 1.0f/262144.0f;
    d_Hb [idx] = make_float2(hr*sc, hi*sc);
    d_Hb2[idx] = make_float2((hr*hr - hi*hi)*sc, 2.0f*hr*hi*sc);
#pragma unroll
    for (int l=0;l<3;l++){
        float a = amp[l*N2+idx], p = phs[l*N2+idx];
        float sn, cs; sincosf(p, &sn, &cs);
        d_Tl[l*N2+idx] = make_float2(a*cs, a*sn);
    }
    unsigned char cl = 255;
#pragma unroll
    for (int q=0;q<10;q++) if (mask[q*N2 + idx] > 0.5f) cl = (unsigned char)q;
    d_cls[idx] = cl;
}

// ---------------- pass kernels ----------------
// Row kernels: 8 rows per 256-thread block; warp = one row; thread = slots j, j+32.

// P1: build E0*T0 in registers, row forward FFT
__global__ void __launch_bounds__(256,4) p1_row(const float* __restrict__ xamp,
                                                const float* __restrict__ pn, int img0){
    __shared__ float2 S[8*RSTRIDE];
    __shared__ float2 TW[NN];
    int t = threadIdx.x;
    TW[t] = d_tw[t]; TW[t+256] = d_tw[t+256];
    int line = t >> 5, j = t & 31;
    int img  = img0 + (blockIdx.x >> 6);
    int row  = ((blockIdx.x & 63) << 3) + line;
    int b = img & 15, m = img >> 4;
    float fm = 0.5f * (float)(m+1);
    size_t ibase = (size_t)img*N2 + (size_t)row*NN;
    size_t bbase = (size_t)b  *N2 + (size_t)row*NN;
    float2 v[8], w[8];
#pragma unroll
    for (int r=0;r<8;r++){
        int e1 = j + 64*r, e2 = j + 32 + 64*r;
        float p1v = pn[ibase + e1], p2v = pn[ibase + e2];
        float x1 = xamp[bbase + e1], x2 = xamp[bbase + e2];
        float sn, cs;
        __sincosf(p1v*fm, &sn, &cs);
        float2 a = make_float2(x1*cs, x1*sn);
        v[r] = cmul(a, d_Tl[row*NN + e1]);
        __sincosf(p2v*fm, &sn, &cs);
        float2 bb = make_float2(x2*cs, x2*sn);
        w[r] = cmul(bb, d_Tl[row*NN + e2]);
    }
    fft512_dual<false,false>(v, w, S + line*RSTRIDE, j, TW);
    BREV_DECL;
#pragma unroll
    for (int r=0;r<8;r++){
        d_field[ibase + j + 64*r]      = v[brev[r]];
        d_field[ibase + j + 32 + 64*r] = w[brev[r]];
    }
}

// col pass: 8 columns per 256-thread block (thread owns adjacent col pair via float4)
__global__ void __launch_bounds__(256,4) col_pass(int h2, int img0){
    __shared__ float2 S[8*CSTRIDE];
    __shared__ float2 TW[NN];
    int t = threadIdx.x;
    TW[t] = d_tw[t]; TW[t+256] = d_tw[t+256];
    int p = t & 3, j = t >> 2;          // pair id, slot
    int img = img0 + (blockIdx.x >> 6);
    int colA = ((blockIdx.x & 63) << 3) + 2*p;
    size_t ibase = (size_t)img*N2;
    BREV_DECL;
    float2 v[8], w[8];
#pragma unroll
    for (int r=0;r<8;r++){
        float4 F = *(const float4*)&d_field[ibase + (size_t)(j+64*r)*NN + colA];
        v[r] = make_float2(F.x, F.y);
        w[r] = make_float2(F.z, F.w);
    }
    float2* sA = S + (2*p  )*CSTRIDE;
    float2* sB = S + (2*p+1)*CSTRIDE;
    fft512_dual2<false,false>(v, w, sA, sB, j, TW);
    // in-place spectral multiply: v[i] holds elem j+64*brev[i]
    const float2* __restrict__ Hm = h2 ? d_Hb2 : d_Hb;
#pragma unroll
    for (int i=0;i<8;i++){
        float4 Hp = *(const float4*)&Hm[(j+64*brev[i])*NN + colA];
        v[i] = cmul(v[i], make_float2(Hp.x, Hp.y));
        w[i] = cmul(w[i], make_float2(Hp.z, Hp.w));
    }
    __syncthreads();    // S free for second FFT
    fft512_dual2<true,true>(v, w, sA, sB, j, TW);
#pragma unroll
    for (int r=0;r<8;r++){
        float4 F;
        F.x = v[brev[r]].x; F.y = v[brev[r]].y;
        F.z = w[brev[r]].x; F.w = w[brev[r]].y;
        *(float4*)&d_field[ibase + (size_t)(j+64*r)*NN + colA] = F;
    }
}

// P3/P5: row inverse FFT (unnormalized), * T_l, row forward FFT
__global__ void __launch_bounds__(256,4) mid_row(int l, int img0){
    __shared__ float2 S[8*RSTRIDE];
    __shared__ float2 TW[NN];
    int t = threadIdx.x;
    TW[t] = d_tw[t]; TW[t+256] = d_tw[t+256];
    int line = t >> 5, j = t & 31;
    int img  = img0 + (blockIdx.x >> 6);
    int row  = ((blockIdx.x & 63) << 3) + line;
    size_t ibase = (size_t)img*N2 + (size_t)row*NN;
    BREV_DECL;
    float2 v[8], w[8];
#pragma unroll
    for (int r=0;r<8;r++){
        v[r] = d_field[ibase + j + 64*r];
        w[r] = d_field[ibase + j + 32 + 64*r];
    }
    float2* s = S + line*RSTRIDE;
    fft512_dual<true,false>(v, w, s, j, TW);
    const float2* __restrict__ T = d_Tl + l*N2 + row*NN;
#pragma unroll
    for (int i=0;i<8;i++){
        v[i] = cmul(v[i], T[j + 64*brev[i]]);
        w[i] = cmul(w[i], T[j + 32 + 64*brev[i]]);
    }
    __syncthreads();
    fft512_dual<false,true>(v, w, s, j, TW);
#pragma unroll
    for (int r=0;r<8;r++){
        d_field[ibase + j + 64*r]      = v[brev[r]];
        d_field[ibase + j + 32 + 64*r] = w[brev[r]];
    }
}

// P7: row inverse FFT, |.|^2, in-block class binning (deterministic)
__global__ void __launch_bounds__(256,4) p7_row(int img0){
    __shared__ float2 S[8*RSTRIDE];
    __shared__ float2 TW[NN];
    __shared__ float WP[8][10];
    int t = threadIdx.x;
    TW[t] = d_tw[t]; TW[t+256] = d_tw[t+256];
    int line = t >> 5, j = t & 31;
    int img  = img0 + (blockIdx.x >> 6);
    int chunk = blockIdx.x & 63;
    int row  = (chunk << 3) + line;
    size_t ibase = (size_t)img*N2 + (size_t)row*NN;
    BREV_DECL;
    float2 v[8], w[8];
#pragma unroll
    for (int r=0;r<8;r++){
        v[r] = d_field[ibase + j + 64*r];
        w[r] = d_field[ibase + j + 32 + 64*r];
    }
    fft512_dual<true,false>(v, w, S + line*RSTRIDE, j, TW);

    float acc[10];
#pragma unroll
    for (int q=0;q<10;q++) acc[q] = 0.f;
#pragma unroll
    for (int i=0;i<8;i++){
        float2 f = v[i];
        float I = f.x*f.x + f.y*f.y;
        int cl = d_cls[row*NN + j + 64*brev[i]];
#pragma unroll
        for (int q=0;q<10;q++) if (cl==q) acc[q] += I;
        f = w[i];
        I = f.x*f.x + f.y*f.y;
        cl = d_cls[row*NN + j + 32 + 64*brev[i]];
#pragma unroll
        for (int q=0;q<10;q++) if (cl==q) acc[q] += I;
    }
#pragma unroll
    for (int q=0;q<10;q++){
#pragma unroll
        for (int o=16;o>0;o>>=1)
            acc[q] += __shfl_xor_sync(0xffffffffu, acc[q], o);
    }
    if (j == 0){
#pragma unroll
        for (int q=0;q<10;q++) WP[line][q] = acc[q];
    }
    __syncthreads();
    if (t < 10){
        float s = 0.f;
#pragma unroll
        for (int q=0;q<8;q++) s += WP[q][t];
        d_part[(img*64 + chunk)*10 + t] = s;
    }
}

// final: sum over 9 modes x 64 chunks, /9, scores [16,10]
__global__ void redB(float* __restrict__ out){
    __shared__ float sh[64];
    int t = threadIdx.x;
    int b = blockIdx.x / 10, c = blockIdx.x % 10;
    float s = 0.f;
#pragma unroll
    for (int m=0;m<9;m++)
        s += d_part[(((m*16+b) << 6) + t)*10 + c];
    sh[t] = s; __syncthreads();
    for (int w=32; w>0; w>>=1){ if (t < w) sh[t] += sh[t+w]; __syncthreads(); }
    if (t==0) out[blockIdx.x] = sh[0] * (1.0f/9.0f);
}

// ---------------- launch ----------------
extern "C" void kernel_launch(void* const* d_in, const int* in_sizes, int n_in,
                              void* d_out, int out_size){
    const float* x_amp  = (const float*)d_in[0];
    const float* pnoise = (const float*)d_in[1];
    const float* amp    = (const float*)d_in[2];
    const float* phs    = (const float*)d_in[3];
    const float* mask   = (const float*)d_in[4];
    float* out = (float*)d_out;

    k_tw  <<<1,   512>>>();
    k_init<<<512, 512>>>(amp, phs, mask);

    const int G = 36;                       // 36 img * 2MB = 72MB, fits L2
    for (int g = 0; g < NIMG/G; g++){
        int i0 = g*G;
        p1_row  <<<G*64, 256>>>(x_amp, pnoise, i0);
        col_pass<<<G*64, 256>>>(0, i0);     // *H/N^2
        mid_row <<<G*64, 256>>>(1, i0);     // *T1
        col_pass<<<G*64, 256>>>(0, i0);     // *H/N^2
        mid_row <<<G*64, 256>>>(2, i0);     // *T2
        col_pass<<<G*64, 256>>>(1, i0);     // *H^2/N^2 (last two props fused)
        p7_row  <<<G*64, 256>>>(i0);
    }
    redB<<<160, 64>>>(out);
}

// round 7
// speedup vs baseline: 1.7580x; 1.0168x over previous
#include <cuda_runtime.h>

#define PI_D 3.14159265358979323846
#define NN   512
#define N2   262144
#define NIMG 144
#define GSIZE 24          // images per pipeline group
#define NG    6           // number of groups
#define BPS   (GSIZE*64)  // blocks per pass-slice = 1536
#define RSTRIDE 584       // row kernels: warp stays within one region
#define CSTRIDE 578       // col kernels: conflict-free across regions
#define SK(i) ((i) + ((i)>>3))

// ---------------- device scratch (no allocations allowed) ----------------
static __device__ float2 d_field[(size_t)NIMG*N2];   // ~302 MB, in-place field
static __device__ float2 d_Tl[3*N2];                 // layer transmissions
static __device__ float2 d_Hb[N2];                   // H / N^2
static __device__ float2 d_Hb2[N2];                  // H^2 / N^2
static __device__ float2 d_tw[NN];                   // e^{-2pi i k/512}
static __device__ unsigned char d_cls[N2];           // pixel -> class (255 = none)
static __device__ float d_part[NIMG*64*10];          // per-block class partials

__device__ __forceinline__ float2 cmul(float2 a, float2 b){
    return make_float2(a.x*b.x - a.y*b.y, a.x*b.y + a.y*b.x);
}

#define BREV_DECL const int brev[8] = {0,4,2,6,1,5,3,7}

// ---------------- radix-8 butterfly (DIF, output bit-reversed) ----------------
template<bool INV>
__device__ __forceinline__ void fft8(float2 v[8]){
    const float C0 = 0.70710678118654752440f;
    float2 t;
#define BTF(a,b) { t = a; a.x = t.x + b.x; a.y = t.y + b.y; b.x = t.x - b.x; b.y = t.y - b.y; }
    BTF(v[0],v[4]); BTF(v[1],v[5]); BTF(v[2],v[6]); BTF(v[3],v[7]);
    if (INV){
        v[5] = cmul(v[5], make_float2(C0,  C0));
        v[6] = make_float2(-v[6].y,  v[6].x);
        v[7] = cmul(v[7], make_float2(-C0, C0));
    } else {
        v[5] = cmul(v[5], make_float2(C0, -C0));
        v[6] = make_float2( v[6].y, -v[6].x);
        v[7] = cmul(v[7], make_float2(-C0,-C0));
    }
    BTF(v[0],v[2]); BTF(v[1],v[3]); BTF(v[4],v[6]); BTF(v[5],v[7]);
    if (INV){ v[3] = make_float2(-v[3].y, v[3].x); v[7] = make_float2(-v[7].y, v[7].x); }
    else    { v[3] = make_float2( v[3].y,-v[3].x); v[7] = make_float2( v[7].y,-v[7].x); }
    BTF(v[0],v[1]); BTF(v[2],v[3]); BTF(v[4],v[5]); BTF(v[6],v[7]);
#undef BTF
}

// apply brev permutation in registers (pure renaming, elided by ptxas)
__device__ __forceinline__ void permute_brev(float2 v[8]){
    BREV_DECL;
    float2 t[8];
#pragma unroll
    for (int r=0;r<8;r++) t[r] = v[brev[r]];
#pragma unroll
    for (int r=0;r<8;r++) v[r] = t[r];
}

// ---- dual-slot 512-pt FFT, ONE line, thread owns slots j and j+32 (j in 0..31)
template<bool INV, bool PERM>
__device__ __forceinline__ void fft512_dual(float2 v[8], float2 w[8],
                                            float2* s, int j, const float2* tw){
    BREV_DECL;
    if (PERM){ permute_brev(v); permute_brev(w); }
    fft8<INV>(v); fft8<INV>(w);
#pragma unroll
    for (int r=0;r<8;r++){ s[SK(8*j+r)] = v[brev[r]]; s[SK(8*(j+32)+r)] = w[brev[r]]; }
    __syncthreads();
#pragma unroll
    for (int r=0;r<8;r++){ v[r] = s[SK(j+64*r)]; w[r] = s[SK(j+32+64*r)]; }
    int jm = j & 7;
#pragma unroll
    for (int r=1;r<8;r++){
        float2 q = tw[r*jm*8];
        if (INV) q.y = -q.y;
        v[r] = cmul(v[r], q); w[r] = cmul(w[r], q);   // (j+32)&7 == j&7
    }
    fft8<INV>(v); fft8<INV>(w);
    int iv = ((j - jm) << 3) + jm;
    int iw = iv + 256;
    __syncthreads();
#pragma unroll
    for (int r=0;r<8;r++){ s[SK(iv + 8*r)] = v[brev[r]]; s[SK(iw + 8*r)] = w[brev[r]]; }
    __syncthreads();
#pragma unroll
    for (int r=0;r<8;r++){ v[r] = s[SK(j+64*r)]; w[r] = s[SK(j+32+64*r)]; }
#pragma unroll
    for (int r=1;r<8;r++){
        float2 qv = tw[r*j], qw = tw[r*(j+32)];
        if (INV){ qv.y = -qv.y; qw.y = -qw.y; }
        v[r] = cmul(v[r], qv); w[r] = cmul(w[r], qw);
    }
    fft8<INV>(v); fft8<INV>(w);
}

// ---- dual-line 512-pt FFT: TWO independent lines (regions sA, sB), slot j (0..63)
template<bool INV, bool PERM>
__device__ __forceinline__ void fft512_dual2(float2 v[8], float2 w[8],
                                             float2* sA, float2* sB, int j,
                                             const float2* tw){
    BREV_DECL;
    if (PERM){ permute_brev(v); permute_brev(w); }
    fft8<INV>(v); fft8<INV>(w);
#pragma unroll
    for (int r=0;r<8;r++){ sA[SK(8*j+r)] = v[brev[r]]; sB[SK(8*j+r)] = w[brev[r]]; }
    __syncthreads();
#pragma unroll
    for (int r=0;r<8;r++){ v[r] = sA[SK(j+64*r)]; w[r] = sB[SK(j+64*r)]; }
    int jm = j & 7;
#pragma unroll
    for (int r=1;r<8;r++){
        float2 q = tw[r*jm*8];
        if (INV) q.y = -q.y;
        v[r] = cmul(v[r], q); w[r] = cmul(w[r], q);
    }
    fft8<INV>(v); fft8<INV>(w);
    int idxD = ((j - jm) << 3) + jm;
    __syncthreads();
#pragma unroll
    for (int r=0;r<8;r++){ sA[SK(idxD + 8*r)] = v[brev[r]]; sB[SK(idxD + 8*r)] = w[brev[r]]; }
    __syncthreads();
#pragma unroll
    for (int r=0;r<8;r++){ v[r] = sA[SK(j+64*r)]; w[r] = sB[SK(j+64*r)]; }
#pragma unroll
    for (int r=1;r<8;r++){
        float2 q = tw[r*j];
        if (INV) q.y = -q.y;
        v[r] = cmul(v[r], q); w[r] = cmul(w[r], q);
    }
    fft8<INV>(v); fft8<INV>(w);
}

// ---------------- init kernels ----------------
__global__ void k_tw(){
    int t = threadIdx.x;
    double ang = -2.0*PI_D*(double)t/512.0;
    d_tw[t] = make_float2((float)cos(ang), (float)sin(ang));
}

__global__ void k_init(const float* __restrict__ amp, const float* __restrict__ phs,
                       const float* __restrict__ mask){
    int i = blockIdx.x, j = threadIdx.x;
    int idx = i*NN + j;
    float inv = 1.0f/(512.0f*8e-6f);
    float fx = (float)(i<256 ? i : i-512) * inv;
    float fy = (float)(j<256 ? j : j-512) * inv;
    const float lam = 5.32e-7f;
    float lx = lam*fx, ly = lam*fy;
    float arg = 1.0f - lx*lx - ly*ly;
    float sa = sqrtf(fmaxf(arg, 0.0f));
    const float KZ = (float)(2.0*PI_D/5.32e-7*0.05);
    float phi = KZ * sa;                   // f32 rounding, matches jax path
    double s, c;
    sincos((double)phi, &s, &c);           // accurate for huge args
    float hr = (float)c, hi = (float)s;
    const float sc = 1.0f/262144.0f;
    d_Hb [idx] = make_float2(hr*sc, hi*sc);
    d_Hb2[idx] = make_float2((hr*hr - hi*hi)*sc, 2.0f*hr*hi*sc);
#pragma unroll
    for (int l=0;l<3;l++){
        float a = amp[l*N2+idx], p = phs[l*N2+idx];
        float sn, cs; sincosf(p, &sn, &cs);
        d_Tl[l*N2+idx] = make_float2(a*cs, a*sn);
    }
    unsigned char cl = 255;
#pragma unroll
    for (int q=0;q<10;q++) if (mask[q*N2 + idx] > 0.5f) cl = (unsigned char)q;
    d_cls[idx] = cl;
}

// ---------------- pass bodies (device functions) ----------------

__device__ __forceinline__ void body_p1(float2* S, float2* TW,
                                        const float* __restrict__ xamp,
                                        const float* __restrict__ pn,
                                        int inner, int img0){
    int t = threadIdx.x;
    int line = t >> 5, j = t & 31;
    int img  = img0 + (inner >> 6);
    int row  = ((inner & 63) << 3) + line;
    int b = img & 15, m = img >> 4;
    float fm = 0.5f * (float)(m+1);
    size_t ibase = (size_t)img*N2 + (size_t)row*NN;
    size_t bbase = (size_t)b  *N2 + (size_t)row*NN;
    float2 v[8], w[8];
#pragma unroll
    for (int r=0;r<8;r++){
        int e1 = j + 64*r, e2 = j + 32 + 64*r;
        float p1v = pn[ibase + e1], p2v = pn[ibase + e2];
        float x1 = xamp[bbase + e1], x2 = xamp[bbase + e2];
        float sn, cs;
        __sincosf(p1v*fm, &sn, &cs);
        float2 a = make_float2(x1*cs, x1*sn);
        v[r] = cmul(a, d_Tl[row*NN + e1]);
        __sincosf(p2v*fm, &sn, &cs);
        float2 bb = make_float2(x2*cs, x2*sn);
        w[r] = cmul(bb, d_Tl[row*NN + e2]);
    }
    fft512_dual<false,false>(v, w, S + line*RSTRIDE, j, TW);
    BREV_DECL;
#pragma unroll
    for (int r=0;r<8;r++){
        d_field[ibase + j + 64*r]      = v[brev[r]];
        d_field[ibase + j + 32 + 64*r] = w[brev[r]];
    }
}

__device__ __forceinline__ void body_col(float2* S, float2* TW,
                                         const float2* __restrict__ Hm,
                                         int inner, int img0){
    int t = threadIdx.x;
    int p = t & 3, j = t >> 2;          // pair id, slot
    int img = img0 + (inner >> 6);
    int colA = ((inner & 63) << 3) + 2*p;
    size_t ibase = (size_t)img*N2;
    BREV_DECL;
    float2 v[8], w[8];
#pragma unroll
    for (int r=0;r<8;r++){
        float4 F = *(const float4*)&d_field[ibase + (size_t)(j+64*r)*NN + colA];
        v[r] = make_float2(F.x, F.y);
        w[r] = make_float2(F.z, F.w);
    }
    float2* sA = S + (2*p  )*CSTRIDE;
    float2* sB = S + (2*p+1)*CSTRIDE;
    fft512_dual2<false,false>(v, w, sA, sB, j, TW);
    // in-place spectral multiply: v[i] holds elem j+64*brev[i]
#pragma unroll
    for (int i=0;i<8;i++){
        float4 Hp = *(const float4*)&Hm[(j+64*brev[i])*NN + colA];
        v[i] = cmul(v[i], make_float2(Hp.x, Hp.y));
        w[i] = cmul(w[i], make_float2(Hp.z, Hp.w));
    }
    __syncthreads();    // S free for second FFT
    fft512_dual2<true,true>(v, w, sA, sB, j, TW);
#pragma unroll
    for (int r=0;r<8;r++){
        float4 F;
        F.x = v[brev[r]].x; F.y = v[brev[r]].y;
        F.z = w[brev[r]].x; F.w = w[brev[r]].y;
        *(float4*)&d_field[ibase + (size_t)(j+64*r)*NN + colA] = F;
    }
}

__device__ __forceinline__ void body_mid(float2* S, float2* TW, int l,
                                         int inner, int img0){
    int t = threadIdx.x;
    int line = t >> 5, j = t & 31;
    int img  = img0 + (inner >> 6);
    int row  = ((inner & 63) << 3) + line;
    size_t ibase = (size_t)img*N2 + (size_t)row*NN;
    BREV_DECL;
    float2 v[8], w[8];
#pragma unroll
    for (int r=0;r<8;r++){
        v[r] = d_field[ibase + j + 64*r];
        w[r] = d_field[ibase + j + 32 + 64*r];
    }
    float2* s = S + line*RSTRIDE;
    fft512_dual<true,false>(v, w, s, j, TW);
    const float2* __restrict__ T = d_Tl + l*N2 + row*NN;
#pragma unroll
    for (int i=0;i<8;i++){
        v[i] = cmul(v[i], T[j + 64*brev[i]]);
        w[i] = cmul(w[i], T[j + 32 + 64*brev[i]]);
    }
    __syncthreads();
    fft512_dual<false,true>(v, w, s, j, TW);
#pragma unroll
    for (int r=0;r<8;r++){
        d_field[ibase + j + 64*r]      = v[brev[r]];
        d_field[ibase + j + 32 + 64*r] = w[brev[r]];
    }
}

__device__ __forceinline__ void body_p7(float2* S, float2* TW, float (*WP)[10],
                                        int inner, int img0){
    int t = threadIdx.x;
    int line = t >> 5, j = t & 31;
    int img  = img0 + (inner >> 6);
    int chunk = inner & 63;
    int row  = (chunk << 3) + line;
    size_t ibase = (size_t)img*N2 + (size_t)row*NN;
    BREV_DECL;
    float2 v[8], w[8];
#pragma unroll
    for (int r=0;r<8;r++){
        v[r] = d_field[ibase + j + 64*r];
        w[r] = d_field[ibase + j + 32 + 64*r];
    }
    fft512_dual<true,false>(v, w, S + line*RSTRIDE, j, TW);

    float acc[10];
#pragma unroll
    for (int q=0;q<10;q++) acc[q] = 0.f;
#pragma unroll
    for (int i=0;i<8;i++){
        float2 f = v[i];
        float I = f.x*f.x + f.y*f.y;
        int cl = d_cls[row*NN + j + 64*brev[i]];
#pragma unroll
        for (int q=0;q<10;q++) if (cl==q) acc[q] += I;
        f = w[i];
        I = f.x*f.x + f.y*f.y;
        cl = d_cls[row*NN + j + 32 + 64*brev[i]];
#pragma unroll
        for (int q=0;q<10;q++) if (cl==q) acc[q] += I;
    }
#pragma unroll
    for (int q=0;q<10;q++){
#pragma unroll
        for (int o=16;o>0;o>>=1)
            acc[q] += __shfl_xor_sync(0xffffffffu, acc[q], o);
    }
    if (j == 0){
#pragma unroll
        for (int q=0;q<10;q++) WP[line][q] = acc[q];
    }
    __syncthreads();
    if (t < 10){
        float s = 0.f;
#pragma unroll
        for (int q=0;q<8;q++) s += WP[q][t];
        d_part[(img*64 + chunk)*10 + t] = s;
    }
}

// ---------------- mega kernel: software-pipelined pass dispatch ----------------
// Launch i contains pass p = i - g for every group g with 0 <= i-g <= 6.
// Slices within a launch touch disjoint image ranges -> independent.
__global__ void __launch_bounds__(256,4) mega(int i, int gmin,
                                              const float* __restrict__ xamp,
                                              const float* __restrict__ pn){
    __shared__ float2 S[8*RSTRIDE];   // RSTRIDE >= CSTRIDE
    __shared__ float2 TW[NN];
    __shared__ float WP[8][10];
    int t = threadIdx.x;
    TW[t] = d_tw[t]; TW[t+256] = d_tw[t+256];

    int slice = blockIdx.x / BPS;
    int inner = blockIdx.x - slice * BPS;
    int g = gmin + slice;
    int p = i - g;
    int img0 = g * GSIZE;

    switch (p){
        case 0: body_p1 (S, TW, xamp, pn, inner, img0); break;
        case 1: body_col(S, TW, d_Hb,  inner, img0); break;
        case 2: body_mid(S, TW, 1,     inner, img0); break;
        case 3: body_col(S, TW, d_Hb,  inner, img0); break;
        case 4: body_mid(S, TW, 2,     inner, img0); break;
        case 5: body_col(S, TW, d_Hb2, inner, img0); break;   // fused last two props
        default: body_p7(S, TW, WP,    inner, img0); break;
    }
}

// final: sum over 9 modes x 64 chunks, /9, scores [16,10]
__global__ void redB(float* __restrict__ out){
    __shared__ float sh[64];
    int t = threadIdx.x;
    int b = blockIdx.x / 10, c = blockIdx.x % 10;
    float s = 0.f;
#pragma unroll
    for (int m=0;m<9;m++)
        s += d_part[(((m*16+b) << 6) + t)*10 + c];
    sh[t] = s; __syncthreads();
    for (int w=32; w>0; w>>=1){ if (t < w) sh[t] += sh[t+w]; __syncthreads(); }
    if (t==0) out[blockIdx.x] = sh[0] * (1.0f/9.0f);
}

// ---------------- launch ----------------
extern "C" void kernel_launch(void* const* d_in, const int* in_sizes, int n_in,
                              void* d_out, int out_size){
    const float* x_amp  = (const float*)d_in[0];
    const float* pnoise = (const float*)d_in[1];
    const float* amp    = (const float*)d_in[2];
    const float* phs    = (const float*)d_in[3];
    const float* mask   = (const float*)d_in[4];
    float* out = (float*)d_out;

    k_tw  <<<1,   512>>>();
    k_init<<<512, 512>>>(amp, phs, mask);

    // pipelined schedule: launch i runs pass (i-g) of group g for all valid g
    for (int i = 0; i < NG + 6; i++){
        int gmin = (i > 6) ? (i - 6) : 0;
        int gmax = (i < NG-1) ? i : (NG-1);
        int ns = gmax - gmin + 1;
        mega<<<ns*BPS, 256>>>(i, gmin, x_amp, pnoise);
    }
    redB<<<160, 64>>>(out);
}